// round 14
// baseline (speedup 1.0000x reference)
#include <cuda_runtime.h>
#include <math.h>

#define TSEQ 256
#define EDIM 1024
#define HDIM 2048
#define G4H  8192
#define G4E  4096
#define CLSD 512
#define MIXD 384
#define NBLK 148
#define NTHR 512

#define ENC_RES 6                      // fp32 units resident per encoder block
#define ENC_RES_TOT (NBLK*ENC_RES)     // 888
#define ENC_SPLIT 124                  // blocks with 8 streamed units (rest 7)

#define DEC_RES 13                     // fp32 units resident per decoder block
#define DEC_RES_TOT (NBLK*DEC_RES)     // 1924
#define DEC_STREAM (2*EDIM - DEC_RES_TOT) // 124

#define ENC_SMEM (ENC_RES*4*HDIM*4 + 2*HDIM*4)            // 212992
#define DEC_SMEM (DEC_RES*4*EDIM*4 + 2*EDIM*4 + 2*EDIM*4) // 229376

// output layout offsets (float elements)
#define OFF_LATF 0
#define OFF_LATR 640
#define OFF_RECF 1280
#define OFF_RECR (1280 + TSEQ*EDIM)
#define OFF_EMBF (OFF_RECR + TSEQ*EDIM)
#define OFF_EMBR (OFF_EMBF + TSEQ*EDIM)

// ---------------- scratch ----------------------------------------------------
__device__ __align__(16) float d_embf[TSEQ*EDIM];
__device__ __align__(16) float d_gpre[TSEQ*G4H];   // layout: [t][unit m][gate 0..3]
__device__ __align__(16) float d_h[2*HDIM];
__device__ __align__(16) float d_hc0[2*EDIM];
__device__ __align__(16) float d_dech[2*EDIM];
__device__ __align__(16) float d_Wsum[2u*G4E*EDIM];     // only streamed rows used now
__device__ __align__(16) float d_bsumd[2*G4E];
__device__ __align__(16) float d_common[CLSD];
__device__ __align__(16) float d_latf[CLSD];
__device__ __align__(16) float d_latr[CLSD];

__device__ unsigned g_bar_count = 0;
__device__ unsigned g_bar_sense = 0;

// R5-proven barrier (exact)
__device__ __forceinline__ void grid_barrier(unsigned nblk, unsigned& sense) {
    __syncthreads();
    if (threadIdx.x == 0) {
        unsigned s = sense ^ 1u;
        sense = s;
        __threadfence();
        if (atomicAdd(&g_bar_count, 1u) == nblk - 1u) {
            atomicExch(&g_bar_count, 0u);
            __threadfence();
            atomicExch(&g_bar_sense, s);
        } else {
            while (atomicAdd(&g_bar_sense, 0u) != s) { __nanosleep(32); }
        }
    }
    __syncthreads();
}

__device__ __forceinline__ float sigf(float x) { return 1.0f / (1.0f + expf(-x)); }

// ---------------- K1: embedding gather ---------------------------------------
__global__ void k_gather(const int* __restrict__ x, const float* __restrict__ emb,
                         float* __restrict__ out) {
    int t = blockIdx.x;
    int row = x[t];
    const float4* src = (const float4*)(emb + (size_t)row * EDIM);
    float4* dE = (float4*)(d_embf + (size_t)t * EDIM);
    float4* oF = (float4*)(out + OFF_EMBF + (size_t)t * EDIM);
    float4* oR = (float4*)(out + OFF_EMBR + (size_t)(TSEQ - 1 - t) * EDIM);
    for (int i = threadIdx.x; i < EDIM / 4; i += blockDim.x) {
        float4 v = src[i];
        dE[i] = v; oF[i] = v; oR[i] = v;
    }
}

// ---------------- K2: gpre = Wih@emb_f + bih + bhh  (128x64 tile, 8x4/thr) ---
// writes TRANSPOSED layout d_gpre[t][m][gate]
__global__ void k_gemm_pre(const float* __restrict__ Wih,
                           const float* __restrict__ bih,
                           const float* __restrict__ bhh) {
    __shared__ float As[16][132];
    __shared__ float Bs[16][68];
    int tid = threadIdx.x;
    int jb = blockIdx.x * 128, tb = blockIdx.y * 64;
    int tx = tid & 15, ty = tid >> 4;

    float acc[4][8];
#pragma unroll
    for (int n = 0; n < 4; ++n)
#pragma unroll
        for (int i = 0; i < 8; ++i) acc[n][i] = 0.f;

    for (int k0 = 0; k0 < EDIM; k0 += 16) {
#pragma unroll
        for (int q = 0; q < 2; ++q) {
            int idx = tid * 2 + q;
            int row = idx >> 2, kv = idx & 3;
            float4 a = __ldg((const float4*)(Wih + (size_t)(jb + row) * EDIM + k0 + kv * 4));
            As[kv * 4 + 0][row] = a.x; As[kv * 4 + 1][row] = a.y;
            As[kv * 4 + 2][row] = a.z; As[kv * 4 + 3][row] = a.w;
        }
        {
            int tl = tid >> 2, kv = tid & 3;
            float4 b = __ldg((const float4*)(d_embf + (size_t)(tb + tl) * EDIM + k0 + kv * 4));
            Bs[kv * 4 + 0][tl] = b.x; Bs[kv * 4 + 1][tl] = b.y;
            Bs[kv * 4 + 2][tl] = b.z; Bs[kv * 4 + 3][tl] = b.w;
        }
        __syncthreads();
#pragma unroll
        for (int k = 0; k < 16; ++k) {
            float a0[8], b0[4];
            float4 av0 = *(const float4*)&As[k][tx * 8];
            float4 av1 = *(const float4*)&As[k][tx * 8 + 4];
            a0[0] = av0.x; a0[1] = av0.y; a0[2] = av0.z; a0[3] = av0.w;
            a0[4] = av1.x; a0[5] = av1.y; a0[6] = av1.z; a0[7] = av1.w;
            float4 bv = *(const float4*)&Bs[k][ty * 4];
            b0[0] = bv.x; b0[1] = bv.y; b0[2] = bv.z; b0[3] = bv.w;
#pragma unroll
            for (int n = 0; n < 4; ++n)
#pragma unroll
                for (int i = 0; i < 8; ++i)
                    acc[n][i] += a0[i] * b0[n];
        }
        __syncthreads();
    }

#pragma unroll
    for (int n = 0; n < 4; ++n) {
        int t = tb + ty * 4 + n;
#pragma unroll
        for (int i = 0; i < 8; ++i) {
            int j = jb + tx * 8 + i;
            int g = j >> 11;          // gate
            int mu = j & 2047;        // unit
            d_gpre[(size_t)t * G4H + (size_t)mu * 4 + g] =
                acc[n][i] + __ldg(&bih[j]) + __ldg(&bhh[j]);
        }
    }
}

// ---------------- K2b: wsum for STREAMED decoder units only + bias sums ------
// streamed units u = 1924..2047, all dir 1 (mm = 900..1023)
__global__ void k_wsum_small(const float* __restrict__ wr_ih, const float* __restrict__ wr_hh,
                             const float* __restrict__ bf_ih, const float* __restrict__ bf_hh,
                             const float* __restrict__ br_ih, const float* __restrict__ br_hh) {
    int gt = blockIdx.x * blockDim.x + threadIdx.x;
    const int NV = DEC_STREAM * 4 * (EDIM / 4);   // 126976 float4s
    if (gt < NV) {
        int r = gt >> 8;            // row 0..495  (su*4+g ordering)
        int k4 = gt & 255;
        int su = r >> 2, g = r & 3;
        int mm = (DEC_RES_TOT - EDIM) + su;       // 900 + su
        size_t row = (size_t)(g * EDIM + mm) * EDIM;
        float4 a = __ldg((const float4*)(wr_ih + row) + k4);
        float4 b = __ldg((const float4*)(wr_hh + row) + k4);
        float4 s;
        s.x = a.x + b.x; s.y = a.y + b.y; s.z = a.z + b.z; s.w = a.w + b.w;
        *((float4*)(d_Wsum + (size_t)G4E * EDIM + row) + k4) = s;
    }
    if (gt < G4E) {
        d_bsumd[gt] = bf_ih[gt] + bf_hh[gt];
        d_bsumd[G4E + gt] = br_ih[gt] + br_hh[gt];
    }
}

// ---------------- K3: encoder persistent (R13 body + gpre hoist) -------------
__global__ void __launch_bounds__(NTHR, 1) k_encoder(const float* __restrict__ Whh) {
    extern __shared__ char esm[];
    float* sm_w = (float*)esm;
    float* sh_h = (float*)(esm + ENC_RES * 4 * HDIM * 4);

    int bid = blockIdx.x, tid = threadIdx.x;
    int warp = tid >> 5, lane = tid & 31;

    for (int i = tid; i < ENC_RES * 4 * HDIM / 4; i += NTHR) {
        int off = i * 4;
        int ul = off >> 13;
        int rem = off & 8191;
        int g = rem >> 11;
        int k = rem & 2047;
        int grow = g * HDIM + bid * ENC_RES + ul;
        ((float4*)sm_w)[i] = __ldg((const float4*)(Whh + (size_t)grow * HDIM + k));
    }

    unsigned sense = (tid == 0) ? atomicAdd(&g_bar_sense, 0u) : 0u;

    for (int i = bid * NTHR + tid; i < 2 * HDIM; i += NBLK * NTHR) d_h[i] = 0.f;

    int s_b = (bid < ENC_SPLIT) ? 8 : 7;
    int sbase = ENC_RES_TOT + bid * 7 + (bid < ENC_SPLIT ? bid : ENC_SPLIT);
    int u_b = ENC_RES + s_b;

    bool active = (warp < u_b);
    bool resident = (warp < ENC_RES);
    int m = resident ? (bid * ENC_RES + warp) : (sbase + warp - ENC_RES);
    if (!active) m = 0;

    float cf = 0.f, cr = 0.f;

    grid_barrier(NBLK, sense);

    const float4* hf4 = (const float4*)sh_h;
    const float4* hr4 = (const float4*)(sh_h + HDIM);

    for (int t = 0; t < TSEQ; ++t) {
        // gpre prefetch FIRST: overlap its L2 latency with h staging
        float gpf0 = 0, gpf1 = 0, gpf2 = 0, gpf3 = 0;
        float gpr0 = 0, gpr1 = 0, gpr2 = 0, gpr3 = 0;
        if (active && lane == 0) {
            float4 gf = __ldg((const float4*)(d_gpre + (size_t)t * G4H + (size_t)m * 4));
            float4 gr = __ldg((const float4*)(d_gpre + (size_t)(TSEQ - 1 - t) * G4H + (size_t)m * 4));
            gpf0 = gf.x; gpf1 = gf.y; gpf2 = gf.z; gpf3 = gf.w;
            gpr0 = gr.x; gpr1 = gr.y; gpr2 = gr.z; gpr3 = gr.w;
        }
        for (int i = tid; i < (2 * HDIM) / 4; i += NTHR)
            ((float4*)sh_h)[i] = __ldcg(((const float4*)d_h) + i);
        __syncthreads();

        if (active) {
            float accf[4] = {0.f, 0.f, 0.f, 0.f};
            float accr[4] = {0.f, 0.f, 0.f, 0.f};
            if (resident) {
                const float4* wsm = (const float4*)sm_w;
#pragma unroll
                for (int it = 0; it < 16; ++it) {
                    int k4 = it * 32 + lane;
                    float4 hf = hf4[k4];
                    float4 hr = hr4[k4];
#pragma unroll
                    for (int g = 0; g < 4; ++g) {
                        float4 w = wsm[(warp * 4 + g) * 512 + k4];
                        accf[g] += w.x * hf.x + w.y * hf.y + w.z * hf.z + w.w * hf.w;
                        accr[g] += w.x * hr.x + w.y * hr.y + w.z * hr.z + w.w * hr.w;
                    }
                }
            } else {
                const float4* w0 = (const float4*)(Whh + (size_t)(0 * HDIM + m) * HDIM);
                const float4* w1 = (const float4*)(Whh + (size_t)(1 * HDIM + m) * HDIM);
                const float4* w2 = (const float4*)(Whh + (size_t)(2 * HDIM + m) * HDIM);
                const float4* w3 = (const float4*)(Whh + (size_t)(3 * HDIM + m) * HDIM);
#pragma unroll
                for (int it = 0; it < 16; ++it) {
                    int k4 = it * 32 + lane;
                    float4 hf = hf4[k4];
                    float4 hr = hr4[k4];
                    float4 w = __ldg(w0 + k4);
                    accf[0] += w.x * hf.x + w.y * hf.y + w.z * hf.z + w.w * hf.w;
                    accr[0] += w.x * hr.x + w.y * hr.y + w.z * hr.z + w.w * hr.w;
                    w = __ldg(w1 + k4);
                    accf[1] += w.x * hf.x + w.y * hf.y + w.z * hf.z + w.w * hf.w;
                    accr[1] += w.x * hr.x + w.y * hr.y + w.z * hr.z + w.w * hr.w;
                    w = __ldg(w2 + k4);
                    accf[2] += w.x * hf.x + w.y * hf.y + w.z * hf.z + w.w * hf.w;
                    accr[2] += w.x * hr.x + w.y * hr.y + w.z * hr.z + w.w * hr.w;
                    w = __ldg(w3 + k4);
                    accf[3] += w.x * hf.x + w.y * hf.y + w.z * hf.z + w.w * hf.w;
                    accr[3] += w.x * hr.x + w.y * hr.y + w.z * hr.z + w.w * hr.w;
                }
            }
#pragma unroll
            for (int o = 16; o > 0; o >>= 1) {
#pragma unroll
                for (int g = 0; g < 4; ++g) {
                    accf[g] += __shfl_xor_sync(0xffffffffu, accf[g], o);
                    accr[g] += __shfl_xor_sync(0xffffffffu, accr[g], o);
                }
            }
            if (lane == 0) {
                float I = accf[0] + gpf0, F = accf[1] + gpf1;
                float G = accf[2] + gpf2, O = accf[3] + gpf3;
                cf = sigf(F) * cf + sigf(I) * tanhf(G);
                d_h[m] = sigf(O) * tanhf(cf);
                I = accr[0] + gpr0; F = accr[1] + gpr1;
                G = accr[2] + gpr2; O = accr[3] + gpr3;
                cr = sigf(F) * cr + sigf(I) * tanhf(G);
                d_h[HDIM + m] = sigf(O) * tanhf(cr);
            }
        }
        grid_barrier(NBLK, sense);
    }
}

// ---------------- K4a: common/lat heads --------------------------------------
__global__ void k_head1(const float* __restrict__ cls_W, const float* __restrict__ cls_b,
                        const float* __restrict__ latf_W, const float* __restrict__ latf_b,
                        const float* __restrict__ latr_W, const float* __restrict__ latr_b) {
    int gw = (blockIdx.x * blockDim.x + threadIdx.x) >> 5;
    int lane = threadIdx.x & 31;
    int nw = (gridDim.x * blockDim.x) >> 5;
    for (int r = gw; r < 3 * CLSD; r += nw) {
        if (r < CLSD) {
            const float4* w = (const float4*)(cls_W + (size_t)r * (2 * HDIM));
            const float4* h = (const float4*)d_h;
            float acc = 0.f;
#pragma unroll 8
            for (int it = 0; it < (2 * HDIM) / 128; ++it) {
                int k4 = it * 32 + lane;
                float4 a = __ldg(w + k4); float4 b = h[k4];
                acc += a.x * b.x + a.y * b.y + a.z * b.z + a.w * b.w;
            }
#pragma unroll
            for (int o = 16; o > 0; o >>= 1) acc += __shfl_xor_sync(0xffffffffu, acc, o);
            if (lane == 0) d_common[r] = tanhf(acc + cls_b[r]);
        } else if (r < 2 * CLSD) {
            int rr = r - CLSD;
            const float4* w = (const float4*)(latf_W + (size_t)rr * HDIM);
            const float4* h = (const float4*)d_h;
            float acc = 0.f;
#pragma unroll 8
            for (int it = 0; it < HDIM / 128; ++it) {
                int k4 = it * 32 + lane;
                float4 a = __ldg(w + k4); float4 b = h[k4];
                acc += a.x * b.x + a.y * b.y + a.z * b.z + a.w * b.w;
            }
#pragma unroll
            for (int o = 16; o > 0; o >>= 1) acc += __shfl_xor_sync(0xffffffffu, acc, o);
            if (lane == 0) d_latf[rr] = acc + latf_b[rr];
        } else {
            int rr = r - 2 * CLSD;
            const float4* w = (const float4*)(latr_W + (size_t)rr * HDIM);
            const float4* h = (const float4*)(d_h + HDIM);
            float acc = 0.f;
#pragma unroll 8
            for (int it = 0; it < HDIM / 128; ++it) {
                int k4 = it * 32 + lane;
                float4 a = __ldg(w + k4); float4 b = h[k4];
                acc += a.x * b.x + a.y * b.y + a.z * b.z + a.w * b.w;
            }
#pragma unroll
            for (int o = 16; o > 0; o >>= 1) acc += __shfl_xor_sync(0xffffffffu, acc, o);
            if (lane == 0) d_latr[rr] = acc + latr_b[rr];
        }
    }
}

// ---------------- K4b: mix + assemble h0 / lat outputs / boundaries ----------
__global__ void k_head2(const float* __restrict__ mix_W, const float* __restrict__ mix_b,
                        const float* __restrict__ emb_Vg, const float* __restrict__ emb_Jg,
                        const int* __restrict__ Vg, const int* __restrict__ Jg,
                        const float* __restrict__ emb, float* __restrict__ out) {
    __shared__ float sm_mix[MIXD];
    int tid = threadIdx.x, warp = tid >> 5, lane = tid & 31;
    for (int r = warp; r < MIXD; r += blockDim.x / 32) {
        const float4* w = (const float4*)(mix_W + (size_t)r * CLSD);
        const float4* c = (const float4*)d_common;
        float acc = 0.f;
#pragma unroll
        for (int it = 0; it < CLSD / 128; ++it) {
            int k4 = it * 32 + lane;
            float4 a = __ldg(w + k4); float4 b = c[k4];
            acc += a.x * b.x + a.y * b.y + a.z * b.z + a.w * b.w;
        }
#pragma unroll
        for (int o = 16; o > 0; o >>= 1) acc += __shfl_xor_sync(0xffffffffu, acc, o);
        if (lane == 0) sm_mix[r] = acc + mix_b[r];
    }
    __syncthreads();
    int vgi = Vg[0], jgi = Jg[0];
    for (int i = tid; i < EDIM; i += blockDim.x) {
        float vf, vr;
        if (i < 64) { float v = emb_Vg[(size_t)vgi * 64 + i]; vf = v; vr = v; }
        else if (i < 576) { vf = d_latf[i - 64]; vr = d_latr[i - 64]; }
        else if (i < 640) { float v = emb_Jg[(size_t)jgi * 64 + (i - 576)]; vf = v; vr = v; }
        else { float v = sm_mix[i - 640]; vf = v; vr = v; }
        d_hc0[i] = vf;        d_hc0[EDIM + i] = vr;
        d_dech[i] = vf;       d_dech[EDIM + i] = vr;
        if (i < 640) { out[OFF_LATF + i] = vf; out[OFF_LATR + i] = vr; }
    }
    for (int i = tid; i < EDIM; i += blockDim.x) {
        float e0 = emb[i];
        float e1 = emb[EDIM + i];
        out[OFF_RECF + i] = e1;
        out[OFF_RECF + (size_t)(TSEQ - 1) * EDIM + i] = e0;
        out[OFF_RECR + i] = e0;
        out[OFF_RECR + (size_t)(TSEQ - 1) * EDIM + i] = e1;
    }
}

// ---------------- K5: decoder persistent (R13 + in-prologue Wsum) ------------
__global__ void __launch_bounds__(NTHR, 1) k_decoder(
        const float* __restrict__ Wihf, const float* __restrict__ Whhf,
        const float* __restrict__ Wihr, const float* __restrict__ Whhr,
        const float* __restrict__ emb, float* __restrict__ out) {
    extern __shared__ char dsm[];
    float* sm_w = (float*)dsm;                              // [DEC_RES][4][1024]
    float* sh_h = (float*)(dsm + DEC_RES * 4 * EDIM * 4);   // [2][1024]
    float* sh_p = sh_h + 2 * EDIM;                          // [2][1024]

    int bid = blockIdx.x, tid = threadIdx.x;
    int warp = tid >> 5, lane = tid & 31;

    // resident Wsum computed in-place from Wih + Whh (bit-identical to k_wsum)
    for (int i = tid; i < DEC_RES * 4 * EDIM / 4; i += NTHR) {
        int off = i * 4;
        int ul = off >> 12;
        int rem = off & 4095;
        int g = rem >> 10;
        int k = rem & 1023;
        int u = bid * DEC_RES + ul;
        int dir = u >> 10, mm = u & 1023;
        const float* Wi = dir ? Wihr : Wihf;
        const float* Wh = dir ? Whhr : Whhf;
        size_t row = (size_t)(g * EDIM + mm) * EDIM;
        float4 a = __ldg((const float4*)(Wi + row + k));
        float4 b = __ldg((const float4*)(Wh + row + k));
        float4 s;
        s.x = a.x + b.x; s.y = a.y + b.y; s.z = a.z + b.z; s.w = a.w + b.w;
        ((float4*)sm_w)[i] = s;
    }
    for (int i = tid; i < (2 * EDIM) / 4; i += NTHR)
        ((float4*)sh_p)[i] = __ldg(((const float4*)emb) + i);

    unsigned sense = (tid == 0) ? atomicAdd(&g_bar_sense, 0u) : 0u;

    bool need0 = (bid * DEC_RES) < EDIM;
    bool need1 = ((bid * DEC_RES + DEC_RES - 1) >= EDIM) || (bid < DEC_STREAM);

    int u_b = DEC_RES + ((bid < DEC_STREAM) ? 1 : 0);
    bool active = (warp < u_b);
    bool resident = (warp < DEC_RES);
    int u = resident ? (bid * DEC_RES + warp) : (DEC_RES_TOT + bid);
    if (!active) u = 0;
    int dir = u >> 10;
    int m = u & 1023;
    float c_reg = 0.f;
    float bs0 = 0, bs1 = 0, bs2 = 0, bs3 = 0;
    if (active && lane == 0) {
        c_reg = __ldcg(&d_hc0[u]);
        const float* bp = d_bsumd + dir * G4E + m;
        bs0 = __ldg(bp);            bs1 = __ldg(bp + EDIM);
        bs2 = __ldg(bp + 2 * EDIM); bs3 = __ldg(bp + 3 * EDIM);
    }

    const float4* h4 = (const float4*)sh_h;
    const float4* p4 = (const float4*)sh_p;

    for (int s = 0; s < TSEQ - 2; ++s) {
        if (need0)
            for (int i = tid; i < EDIM / 4; i += NTHR)
                ((float4*)sh_h)[i] = __ldcg(((const float4*)d_dech) + i);
        if (need1)
            for (int i = tid; i < EDIM / 4; i += NTHR)
                ((float4*)sh_h)[EDIM / 4 + i] = __ldcg(((const float4*)d_dech) + EDIM / 4 + i);
        __syncthreads();

        if (active) {
            float acc[4] = {0.f, 0.f, 0.f, 0.f};
            if (s == 0) {
                const float* Wi = dir ? Wihr : Wihf;
                const float* Wh = dir ? Whhr : Whhf;
#pragma unroll
                for (int it = 0; it < 8; ++it) {
                    int k4 = it * 32 + lane;
                    float4 p = p4[dir * 256 + k4];
                    float4 h = h4[dir * 256 + k4];
#pragma unroll
                    for (int g = 0; g < 4; ++g) {
                        const float4* wi = (const float4*)(Wi + (size_t)(g * EDIM + m) * EDIM);
                        const float4* wh = (const float4*)(Wh + (size_t)(g * EDIM + m) * EDIM);
                        float4 a = __ldg(wi + k4);
                        acc[g] += a.x * p.x + a.y * p.y + a.z * p.z + a.w * p.w;
                        float4 b = __ldg(wh + k4);
                        acc[g] += b.x * h.x + b.y * h.y + b.z * h.z + b.w * h.w;
                    }
                }
            } else if (resident) {
                const float4* wsm = (const float4*)sm_w;
#pragma unroll
                for (int it = 0; it < 8; ++it) {
                    int k4 = it * 32 + lane;
                    float4 h = h4[dir * 256 + k4];
#pragma unroll
                    for (int g = 0; g < 4; ++g) {
                        float4 w = wsm[(warp * 4 + g) * 256 + k4];
                        acc[g] += w.x * h.x + w.y * h.y + w.z * h.z + w.w * h.w;
                    }
                }
            } else {
                const float* Wb = d_Wsum + (size_t)dir * G4E * EDIM;
#pragma unroll
                for (int it = 0; it < 8; ++it) {
                    int k4 = it * 32 + lane;
                    float4 h = h4[dir * 256 + k4];
#pragma unroll
                    for (int g = 0; g < 4; ++g) {
                        float4 w = __ldg((const float4*)(Wb + (size_t)(g * EDIM + m) * EDIM) + k4);
                        acc[g] += w.x * h.x + w.y * h.y + w.z * h.z + w.w * h.w;
                    }
                }
            }
#pragma unroll
            for (int o = 16; o > 0; o >>= 1) {
#pragma unroll
                for (int g = 0; g < 4; ++g)
                    acc[g] += __shfl_xor_sync(0xffffffffu, acc[g], o);
            }
            if (lane == 0) {
                float I = acc[0] + bs0, F = acc[1] + bs1;
                float G = acc[2] + bs2, O = acc[3] + bs3;
                c_reg = sigf(F) * c_reg + sigf(I) * tanhf(G);
                float h2 = sigf(O) * tanhf(c_reg);
                d_dech[u] = h2;
                size_t off = dir ? (size_t)OFF_RECR : (size_t)OFF_RECF;
                out[off + (size_t)(TSEQ - 2 - s) * EDIM + m] = h2;
            }
        }
        grid_barrier(NBLK, sense);
    }
}

// ---------------- launch ------------------------------------------------------
extern "C" void kernel_launch(void* const* d_in, const int* in_sizes, int n_in,
                              void* d_out, int out_size) {
    (void)in_sizes; (void)n_in; (void)out_size;
    const int*   x       = (const int*)d_in[0];
    const int*   Vg      = (const int*)d_in[1];
    const int*   Jg      = (const int*)d_in[2];
    const float* emb     = (const float*)d_in[3];
    const float* emb_Vg  = (const float*)d_in[4];
    const float* emb_Jg  = (const float*)d_in[5];
    const float* enc_Wih = (const float*)d_in[6];
    const float* enc_Whh = (const float*)d_in[7];
    const float* enc_bih = (const float*)d_in[8];
    const float* enc_bhh = (const float*)d_in[9];
    const float* cls_W   = (const float*)d_in[10];
    const float* cls_b   = (const float*)d_in[11];
    const float* latf_W  = (const float*)d_in[12];
    const float* latf_b  = (const float*)d_in[13];
    const float* latr_W  = (const float*)d_in[14];
    const float* latr_b  = (const float*)d_in[15];
    const float* mix_W   = (const float*)d_in[16];
    const float* mix_b   = (const float*)d_in[17];
    const float* recf_Wih = (const float*)d_in[18];
    const float* recf_Whh = (const float*)d_in[19];
    const float* recf_bih = (const float*)d_in[20];
    const float* recf_bhh = (const float*)d_in[21];
    const float* recr_Wih = (const float*)d_in[22];
    const float* recr_Whh = (const float*)d_in[23];
    const float* recr_bih = (const float*)d_in[24];
    const float* recr_bhh = (const float*)d_in[25];
    float* out = (float*)d_out;

    cudaFuncSetAttribute(k_encoder, cudaFuncAttributeMaxDynamicSharedMemorySize, ENC_SMEM);
    cudaFuncSetAttribute(k_decoder, cudaFuncAttributeMaxDynamicSharedMemorySize, DEC_SMEM);

    k_gather<<<TSEQ, 256>>>(x, emb, out);
    k_gemm_pre<<<dim3(G4H / 128, TSEQ / 64), 256>>>(enc_Wih, enc_bih, enc_bhh);
    k_wsum_small<<<(DEC_STREAM * 4 * (EDIM / 4) + 255) / 256, 256>>>(
        recr_Wih, recr_Whh, recf_bih, recf_bhh, recr_bih, recr_bhh);
    k_encoder<<<NBLK, NTHR, ENC_SMEM>>>(enc_Whh);
    k_head1<<<32, 256>>>(cls_W, cls_b, latf_W, latf_b, latr_W, latr_b);
    k_head2<<<1, 256>>>(mix_W, mix_b, emb_Vg, emb_Jg, Vg, Jg, emb, out);
    k_decoder<<<NBLK, NTHR, DEC_SMEM>>>(recf_Wih, recf_Whh, recr_Wih, recr_Whh, emb, out);
}

// round 15
// speedup vs baseline: 1.0085x; 1.0085x over previous
#include <cuda_runtime.h>
#include <math.h>

#define TSEQ 256
#define EDIM 1024
#define HDIM 2048
#define G4H  8192
#define G4E  4096
#define CLSD 512
#define MIXD 384
#define NBLK 148
#define NTHR 512

#define ENC_RES 6                      // fp32 units resident per encoder block
#define ENC_RES_TOT (NBLK*ENC_RES)     // 888
#define ENC_SPLIT 124                  // blocks with 8 streamed units (rest 7)

#define DEC_RES 13                     // fp32 units resident per decoder block
#define DEC_RES_TOT (NBLK*DEC_RES)     // 1924
#define DEC_STREAM (2*EDIM - DEC_RES_TOT) // 124

#define ENC_SMEM (ENC_RES*4*HDIM*4 + 2*HDIM*4)            // 212992
#define DEC_SMEM (DEC_RES*4*EDIM*4 + 2*EDIM*4 + 2*EDIM*4) // 229376

// output layout offsets (float elements)
#define OFF_LATF 0
#define OFF_LATR 640
#define OFF_RECF 1280
#define OFF_RECR (1280 + TSEQ*EDIM)
#define OFF_EMBF (OFF_RECR + TSEQ*EDIM)
#define OFF_EMBR (OFF_EMBF + TSEQ*EDIM)

// ---------------- scratch ----------------------------------------------------
__device__ __align__(16) float d_embf[TSEQ*EDIM];
__device__ __align__(16) float d_gpre[TSEQ*G4H];   // layout: [t][unit m][gate 0..3]
__device__ __align__(16) float d_h[2*HDIM];
__device__ __align__(16) float d_hc0[2*EDIM];
__device__ __align__(16) float d_dech[2*EDIM];
__device__ __align__(16) float d_Wsum[2u*G4E*EDIM];     // only streamed rows used
__device__ __align__(16) float d_bsumd[2*G4E];
__device__ __align__(16) float d_common[CLSD];
__device__ __align__(16) float d_latf[CLSD];
__device__ __align__(16) float d_latr[CLSD];

__device__ unsigned g_bar_count = 0;
__device__ unsigned g_bar_sense = 0;

// R5-proven barrier (exact)
__device__ __forceinline__ void grid_barrier(unsigned nblk, unsigned& sense) {
    __syncthreads();
    if (threadIdx.x == 0) {
        unsigned s = sense ^ 1u;
        sense = s;
        __threadfence();
        if (atomicAdd(&g_bar_count, 1u) == nblk - 1u) {
            atomicExch(&g_bar_count, 0u);
            __threadfence();
            atomicExch(&g_bar_sense, s);
        } else {
            while (atomicAdd(&g_bar_sense, 0u) != s) { __nanosleep(32); }
        }
    }
    __syncthreads();
}

__device__ __forceinline__ float sigf(float x) { return 1.0f / (1.0f + expf(-x)); }

// ---------------- K1: embedding gather ---------------------------------------
__global__ void k_gather(const int* __restrict__ x, const float* __restrict__ emb,
                         float* __restrict__ out) {
    int t = blockIdx.x;
    int row = x[t];
    const float4* src = (const float4*)(emb + (size_t)row * EDIM);
    float4* dE = (float4*)(d_embf + (size_t)t * EDIM);
    float4* oF = (float4*)(out + OFF_EMBF + (size_t)t * EDIM);
    float4* oR = (float4*)(out + OFF_EMBR + (size_t)(TSEQ - 1 - t) * EDIM);
    for (int i = threadIdx.x; i < EDIM / 4; i += blockDim.x) {
        float4 v = src[i];
        dE[i] = v; oF[i] = v; oR[i] = v;
    }
}

// ---------------- K2: gpre = Wih@emb_f + bih + bhh  (128x64 tile, 8x4/thr) ---
// writes TRANSPOSED layout d_gpre[t][m][gate]
__global__ void k_gemm_pre(const float* __restrict__ Wih,
                           const float* __restrict__ bih,
                           const float* __restrict__ bhh) {
    __shared__ float As[16][132];
    __shared__ float Bs[16][68];
    int tid = threadIdx.x;
    int jb = blockIdx.x * 128, tb = blockIdx.y * 64;
    int tx = tid & 15, ty = tid >> 4;

    float acc[4][8];
#pragma unroll
    for (int n = 0; n < 4; ++n)
#pragma unroll
        for (int i = 0; i < 8; ++i) acc[n][i] = 0.f;

    for (int k0 = 0; k0 < EDIM; k0 += 16) {
#pragma unroll
        for (int q = 0; q < 2; ++q) {
            int idx = tid * 2 + q;
            int row = idx >> 2, kv = idx & 3;
            float4 a = __ldg((const float4*)(Wih + (size_t)(jb + row) * EDIM + k0 + kv * 4));
            As[kv * 4 + 0][row] = a.x; As[kv * 4 + 1][row] = a.y;
            As[kv * 4 + 2][row] = a.z; As[kv * 4 + 3][row] = a.w;
        }
        {
            int tl = tid >> 2, kv = tid & 3;
            float4 b = __ldg((const float4*)(d_embf + (size_t)(tb + tl) * EDIM + k0 + kv * 4));
            Bs[kv * 4 + 0][tl] = b.x; Bs[kv * 4 + 1][tl] = b.y;
            Bs[kv * 4 + 2][tl] = b.z; Bs[kv * 4 + 3][tl] = b.w;
        }
        __syncthreads();
#pragma unroll
        for (int k = 0; k < 16; ++k) {
            float a0[8], b0[4];
            float4 av0 = *(const float4*)&As[k][tx * 8];
            float4 av1 = *(const float4*)&As[k][tx * 8 + 4];
            a0[0] = av0.x; a0[1] = av0.y; a0[2] = av0.z; a0[3] = av0.w;
            a0[4] = av1.x; a0[5] = av1.y; a0[6] = av1.z; a0[7] = av1.w;
            float4 bv = *(const float4*)&Bs[k][ty * 4];
            b0[0] = bv.x; b0[1] = bv.y; b0[2] = bv.z; b0[3] = bv.w;
#pragma unroll
            for (int n = 0; n < 4; ++n)
#pragma unroll
                for (int i = 0; i < 8; ++i)
                    acc[n][i] += a0[i] * b0[n];
        }
        __syncthreads();
    }

#pragma unroll
    for (int n = 0; n < 4; ++n) {
        int t = tb + ty * 4 + n;
#pragma unroll
        for (int i = 0; i < 8; ++i) {
            int j = jb + tx * 8 + i;
            int g = j >> 11;          // gate
            int mu = j & 2047;        // unit
            d_gpre[(size_t)t * G4H + (size_t)mu * 4 + g] =
                acc[n][i] + __ldg(&bih[j]) + __ldg(&bhh[j]);
        }
    }
}

// ---------------- K2b: wsum for STREAMED decoder units only + bias sums ------
// streamed units u = 1924..2047, all dir 1 (mm = 900..1023)
__global__ void k_wsum_small(const float* __restrict__ wr_ih, const float* __restrict__ wr_hh,
                             const float* __restrict__ bf_ih, const float* __restrict__ bf_hh,
                             const float* __restrict__ br_ih, const float* __restrict__ br_hh) {
    int gt = blockIdx.x * blockDim.x + threadIdx.x;
    const int NV = DEC_STREAM * 4 * (EDIM / 4);   // 126976 float4s
    if (gt < NV) {
        int r = gt >> 8;            // row 0..495  (su*4+g ordering)
        int k4 = gt & 255;
        int su = r >> 2, g = r & 3;
        int mm = (DEC_RES_TOT - EDIM) + su;       // 900 + su
        size_t row = (size_t)(g * EDIM + mm) * EDIM;
        float4 a = __ldg((const float4*)(wr_ih + row) + k4);
        float4 b = __ldg((const float4*)(wr_hh + row) + k4);
        float4 s;
        s.x = a.x + b.x; s.y = a.y + b.y; s.z = a.z + b.z; s.w = a.w + b.w;
        *((float4*)(d_Wsum + (size_t)G4E * EDIM + row) + k4) = s;
    }
    if (gt < G4E) {
        d_bsumd[gt] = bf_ih[gt] + bf_hh[gt];
        d_bsumd[G4E + gt] = br_ih[gt] + br_hh[gt];
    }
}

// ---------------- K3: encoder persistent (R13-EXACT body, final-barrier skip)-
__global__ void __launch_bounds__(NTHR, 1) k_encoder(const float* __restrict__ Whh) {
    extern __shared__ char esm[];
    float* sm_w = (float*)esm;
    float* sh_h = (float*)(esm + ENC_RES * 4 * HDIM * 4);

    int bid = blockIdx.x, tid = threadIdx.x;
    int warp = tid >> 5, lane = tid & 31;

    for (int i = tid; i < ENC_RES * 4 * HDIM / 4; i += NTHR) {
        int off = i * 4;
        int ul = off >> 13;
        int rem = off & 8191;
        int g = rem >> 11;
        int k = rem & 2047;
        int grow = g * HDIM + bid * ENC_RES + ul;
        ((float4*)sm_w)[i] = __ldg((const float4*)(Whh + (size_t)grow * HDIM + k));
    }

    unsigned sense = (tid == 0) ? atomicAdd(&g_bar_sense, 0u) : 0u;

    for (int i = bid * NTHR + tid; i < 2 * HDIM; i += NBLK * NTHR) d_h[i] = 0.f;

    int s_b = (bid < ENC_SPLIT) ? 8 : 7;
    int sbase = ENC_RES_TOT + bid * 7 + (bid < ENC_SPLIT ? bid : ENC_SPLIT);
    int u_b = ENC_RES + s_b;

    bool active = (warp < u_b);
    bool resident = (warp < ENC_RES);
    int m = resident ? (bid * ENC_RES + warp) : (sbase + warp - ENC_RES);
    if (!active) m = 0;

    float cf = 0.f, cr = 0.f;

    grid_barrier(NBLK, sense);

    const float4* hf4 = (const float4*)sh_h;
    const float4* hr4 = (const float4*)(sh_h + HDIM);

    for (int t = 0; t < TSEQ; ++t) {
        for (int i = tid; i < (2 * HDIM) / 4; i += NTHR)
            ((float4*)sh_h)[i] = __ldcg(((const float4*)d_h) + i);
        __syncthreads();

        if (active) {
            float gpf0 = 0, gpf1 = 0, gpf2 = 0, gpf3 = 0;
            float gpr0 = 0, gpr1 = 0, gpr2 = 0, gpr3 = 0;
            if (lane == 0) {
                float4 gf = __ldg((const float4*)(d_gpre + (size_t)t * G4H + (size_t)m * 4));
                float4 gr = __ldg((const float4*)(d_gpre + (size_t)(TSEQ - 1 - t) * G4H + (size_t)m * 4));
                gpf0 = gf.x; gpf1 = gf.y; gpf2 = gf.z; gpf3 = gf.w;
                gpr0 = gr.x; gpr1 = gr.y; gpr2 = gr.z; gpr3 = gr.w;
            }

            float accf[4] = {0.f, 0.f, 0.f, 0.f};
            float accr[4] = {0.f, 0.f, 0.f, 0.f};
            if (resident) {
                const float4* wsm = (const float4*)sm_w;
#pragma unroll
                for (int it = 0; it < 16; ++it) {
                    int k4 = it * 32 + lane;
                    float4 hf = hf4[k4];
                    float4 hr = hr4[k4];
#pragma unroll
                    for (int g = 0; g < 4; ++g) {
                        float4 w = wsm[(warp * 4 + g) * 512 + k4];
                        accf[g] += w.x * hf.x + w.y * hf.y + w.z * hf.z + w.w * hf.w;
                        accr[g] += w.x * hr.x + w.y * hr.y + w.z * hr.z + w.w * hr.w;
                    }
                }
            } else {
                const float4* w0 = (const float4*)(Whh + (size_t)(0 * HDIM + m) * HDIM);
                const float4* w1 = (const float4*)(Whh + (size_t)(1 * HDIM + m) * HDIM);
                const float4* w2 = (const float4*)(Whh + (size_t)(2 * HDIM + m) * HDIM);
                const float4* w3 = (const float4*)(Whh + (size_t)(3 * HDIM + m) * HDIM);
#pragma unroll
                for (int it = 0; it < 16; ++it) {
                    int k4 = it * 32 + lane;
                    float4 hf = hf4[k4];
                    float4 hr = hr4[k4];
                    float4 w = __ldg(w0 + k4);
                    accf[0] += w.x * hf.x + w.y * hf.y + w.z * hf.z + w.w * hf.w;
                    accr[0] += w.x * hr.x + w.y * hr.y + w.z * hr.z + w.w * hr.w;
                    w = __ldg(w1 + k4);
                    accf[1] += w.x * hf.x + w.y * hf.y + w.z * hf.z + w.w * hf.w;
                    accr[1] += w.x * hr.x + w.y * hr.y + w.z * hr.z + w.w * hr.w;
                    w = __ldg(w2 + k4);
                    accf[2] += w.x * hf.x + w.y * hf.y + w.z * hf.z + w.w * hf.w;
                    accr[2] += w.x * hr.x + w.y * hr.y + w.z * hr.z + w.w * hr.w;
                    w = __ldg(w3 + k4);
                    accf[3] += w.x * hf.x + w.y * hf.y + w.z * hf.z + w.w * hf.w;
                    accr[3] += w.x * hr.x + w.y * hr.y + w.z * hr.z + w.w * hr.w;
                }
            }
#pragma unroll
            for (int o = 16; o > 0; o >>= 1) {
#pragma unroll
                for (int g = 0; g < 4; ++g) {
                    accf[g] += __shfl_xor_sync(0xffffffffu, accf[g], o);
                    accr[g] += __shfl_xor_sync(0xffffffffu, accr[g], o);
                }
            }
            if (lane == 0) {
                float I = accf[0] + gpf0, F = accf[1] + gpf1;
                float G = accf[2] + gpf2, O = accf[3] + gpf3;
                cf = sigf(F) * cf + sigf(I) * tanhf(G);
                d_h[m] = sigf(O) * tanhf(cf);
                I = accr[0] + gpr0; F = accr[1] + gpr1;
                G = accr[2] + gpr2; O = accr[3] + gpr3;
                cr = sigf(F) * cr + sigf(I) * tanhf(G);
                d_h[HDIM + m] = sigf(O) * tanhf(cr);
            }
        }
        if (t < TSEQ - 1) grid_barrier(NBLK, sense);
    }
}

// ---------------- K4a: common/lat heads --------------------------------------
__global__ void k_head1(const float* __restrict__ cls_W, const float* __restrict__ cls_b,
                        const float* __restrict__ latf_W, const float* __restrict__ latf_b,
                        const float* __restrict__ latr_W, const float* __restrict__ latr_b) {
    int gw = (blockIdx.x * blockDim.x + threadIdx.x) >> 5;
    int lane = threadIdx.x & 31;
    int nw = (gridDim.x * blockDim.x) >> 5;
    for (int r = gw; r < 3 * CLSD; r += nw) {
        if (r < CLSD) {
            const float4* w = (const float4*)(cls_W + (size_t)r * (2 * HDIM));
            const float4* h = (const float4*)d_h;
            float acc = 0.f;
#pragma unroll 8
            for (int it = 0; it < (2 * HDIM) / 128; ++it) {
                int k4 = it * 32 + lane;
                float4 a = __ldg(w + k4); float4 b = h[k4];
                acc += a.x * b.x + a.y * b.y + a.z * b.z + a.w * b.w;
            }
#pragma unroll
            for (int o = 16; o > 0; o >>= 1) acc += __shfl_xor_sync(0xffffffffu, acc, o);
            if (lane == 0) d_common[r] = tanhf(acc + cls_b[r]);
        } else if (r < 2 * CLSD) {
            int rr = r - CLSD;
            const float4* w = (const float4*)(latf_W + (size_t)rr * HDIM);
            const float4* h = (const float4*)d_h;
            float acc = 0.f;
#pragma unroll 8
            for (int it = 0; it < HDIM / 128; ++it) {
                int k4 = it * 32 + lane;
                float4 a = __ldg(w + k4); float4 b = h[k4];
                acc += a.x * b.x + a.y * b.y + a.z * b.z + a.w * b.w;
            }
#pragma unroll
            for (int o = 16; o > 0; o >>= 1) acc += __shfl_xor_sync(0xffffffffu, acc, o);
            if (lane == 0) d_latf[rr] = acc + latf_b[rr];
        } else {
            int rr = r - 2 * CLSD;
            const float4* w = (const float4*)(latr_W + (size_t)rr * HDIM);
            const float4* h = (const float4*)(d_h + HDIM);
            float acc = 0.f;
#pragma unroll 8
            for (int it = 0; it < HDIM / 128; ++it) {
                int k4 = it * 32 + lane;
                float4 a = __ldg(w + k4); float4 b = h[k4];
                acc += a.x * b.x + a.y * b.y + a.z * b.z + a.w * b.w;
            }
#pragma unroll
            for (int o = 16; o > 0; o >>= 1) acc += __shfl_xor_sync(0xffffffffu, acc, o);
            if (lane == 0) d_latr[rr] = acc + latr_b[rr];
        }
    }
}

// ---------------- K4b: mix + assemble h0 / lat outputs / boundaries ----------
__global__ void k_head2(const float* __restrict__ mix_W, const float* __restrict__ mix_b,
                        const float* __restrict__ emb_Vg, const float* __restrict__ emb_Jg,
                        const int* __restrict__ Vg, const int* __restrict__ Jg,
                        const float* __restrict__ emb, float* __restrict__ out) {
    __shared__ float sm_mix[MIXD];
    int tid = threadIdx.x, warp = tid >> 5, lane = tid & 31;
    for (int r = warp; r < MIXD; r += blockDim.x / 32) {
        const float4* w = (const float4*)(mix_W + (size_t)r * CLSD);
        const float4* c = (const float4*)d_common;
        float acc = 0.f;
#pragma unroll
        for (int it = 0; it < CLSD / 128; ++it) {
            int k4 = it * 32 + lane;
            float4 a = __ldg(w + k4); float4 b = c[k4];
            acc += a.x * b.x + a.y * b.y + a.z * b.z + a.w * b.w;
        }
#pragma unroll
        for (int o = 16; o > 0; o >>= 1) acc += __shfl_xor_sync(0xffffffffu, acc, o);
        if (lane == 0) sm_mix[r] = acc + mix_b[r];
    }
    __syncthreads();
    int vgi = Vg[0], jgi = Jg[0];
    for (int i = tid; i < EDIM; i += blockDim.x) {
        float vf, vr;
        if (i < 64) { float v = emb_Vg[(size_t)vgi * 64 + i]; vf = v; vr = v; }
        else if (i < 576) { vf = d_latf[i - 64]; vr = d_latr[i - 64]; }
        else if (i < 640) { float v = emb_Jg[(size_t)jgi * 64 + (i - 576)]; vf = v; vr = v; }
        else { float v = sm_mix[i - 640]; vf = v; vr = v; }
        d_hc0[i] = vf;        d_hc0[EDIM + i] = vr;
        d_dech[i] = vf;       d_dech[EDIM + i] = vr;
        if (i < 640) { out[OFF_LATF + i] = vf; out[OFF_LATR + i] = vr; }
    }
    for (int i = tid; i < EDIM; i += blockDim.x) {
        float e0 = emb[i];
        float e1 = emb[EDIM + i];
        out[OFF_RECF + i] = e1;
        out[OFF_RECF + (size_t)(TSEQ - 1) * EDIM + i] = e0;
        out[OFF_RECR + i] = e0;
        out[OFF_RECR + (size_t)(TSEQ - 1) * EDIM + i] = e1;
    }
}

// ---------------- K5: decoder persistent (R14 body, final-barrier skip) ------
__global__ void __launch_bounds__(NTHR, 1) k_decoder(
        const float* __restrict__ Wihf, const float* __restrict__ Whhf,
        const float* __restrict__ Wihr, const float* __restrict__ Whhr,
        const float* __restrict__ emb, float* __restrict__ out) {
    extern __shared__ char dsm[];
    float* sm_w = (float*)dsm;                              // [DEC_RES][4][1024]
    float* sh_h = (float*)(dsm + DEC_RES * 4 * EDIM * 4);   // [2][1024]
    float* sh_p = sh_h + 2 * EDIM;                          // [2][1024]

    int bid = blockIdx.x, tid = threadIdx.x;
    int warp = tid >> 5, lane = tid & 31;

    // resident Wsum computed in-place from Wih + Whh (bit-identical to k_wsum)
    for (int i = tid; i < DEC_RES * 4 * EDIM / 4; i += NTHR) {
        int off = i * 4;
        int ul = off >> 12;
        int rem = off & 4095;
        int g = rem >> 10;
        int k = rem & 1023;
        int u = bid * DEC_RES + ul;
        int dir = u >> 10, mm = u & 1023;
        const float* Wi = dir ? Wihr : Wihf;
        const float* Wh = dir ? Whhr : Whhf;
        size_t row = (size_t)(g * EDIM + mm) * EDIM;
        float4 a = __ldg((const float4*)(Wi + row + k));
        float4 b = __ldg((const float4*)(Wh + row + k));
        float4 s;
        s.x = a.x + b.x; s.y = a.y + b.y; s.z = a.z + b.z; s.w = a.w + b.w;
        ((float4*)sm_w)[i] = s;
    }
    for (int i = tid; i < (2 * EDIM) / 4; i += NTHR)
        ((float4*)sh_p)[i] = __ldg(((const float4*)emb) + i);

    unsigned sense = (tid == 0) ? atomicAdd(&g_bar_sense, 0u) : 0u;

    bool need0 = (bid * DEC_RES) < EDIM;
    bool need1 = ((bid * DEC_RES + DEC_RES - 1) >= EDIM) || (bid < DEC_STREAM);

    int u_b = DEC_RES + ((bid < DEC_STREAM) ? 1 : 0);
    bool active = (warp < u_b);
    bool resident = (warp < DEC_RES);
    int u = resident ? (bid * DEC_RES + warp) : (DEC_RES_TOT + bid);
    if (!active) u = 0;
    int dir = u >> 10;
    int m = u & 1023;
    float c_reg = 0.f;
    float bs0 = 0, bs1 = 0, bs2 = 0, bs3 = 0;
    if (active && lane == 0) {
        c_reg = __ldcg(&d_hc0[u]);
        const float* bp = d_bsumd + dir * G4E + m;
        bs0 = __ldg(bp);            bs1 = __ldg(bp + EDIM);
        bs2 = __ldg(bp + 2 * EDIM); bs3 = __ldg(bp + 3 * EDIM);
    }

    const float4* h4 = (const float4*)sh_h;
    const float4* p4 = (const float4*)sh_p;

    for (int s = 0; s < TSEQ - 2; ++s) {
        if (need0)
            for (int i = tid; i < EDIM / 4; i += NTHR)
                ((float4*)sh_h)[i] = __ldcg(((const float4*)d_dech) + i);
        if (need1)
            for (int i = tid; i < EDIM / 4; i += NTHR)
                ((float4*)sh_h)[EDIM / 4 + i] = __ldcg(((const float4*)d_dech) + EDIM / 4 + i);
        __syncthreads();

        if (active) {
            float acc[4] = {0.f, 0.f, 0.f, 0.f};
            if (s == 0) {
                const float* Wi = dir ? Wihr : Wihf;
                const float* Wh = dir ? Whhr : Whhf;
#pragma unroll
                for (int it = 0; it < 8; ++it) {
                    int k4 = it * 32 + lane;
                    float4 p = p4[dir * 256 + k4];
                    float4 h = h4[dir * 256 + k4];
#pragma unroll
                    for (int g = 0; g < 4; ++g) {
                        const float4* wi = (const float4*)(Wi + (size_t)(g * EDIM + m) * EDIM);
                        const float4* wh = (const float4*)(Wh + (size_t)(g * EDIM + m) * EDIM);
                        float4 a = __ldg(wi + k4);
                        acc[g] += a.x * p.x + a.y * p.y + a.z * p.z + a.w * p.w;
                        float4 b = __ldg(wh + k4);
                        acc[g] += b.x * h.x + b.y * h.y + b.z * h.z + b.w * h.w;
                    }
                }
            } else if (resident) {
                const float4* wsm = (const float4*)sm_w;
#pragma unroll
                for (int it = 0; it < 8; ++it) {
                    int k4 = it * 32 + lane;
                    float4 h = h4[dir * 256 + k4];
#pragma unroll
                    for (int g = 0; g < 4; ++g) {
                        float4 w = wsm[(warp * 4 + g) * 256 + k4];
                        acc[g] += w.x * h.x + w.y * h.y + w.z * h.z + w.w * h.w;
                    }
                }
            } else {
                const float* Wb = d_Wsum + (size_t)dir * G4E * EDIM;
#pragma unroll
                for (int it = 0; it < 8; ++it) {
                    int k4 = it * 32 + lane;
                    float4 h = h4[dir * 256 + k4];
#pragma unroll
                    for (int g = 0; g < 4; ++g) {
                        float4 w = __ldg((const float4*)(Wb + (size_t)(g * EDIM + m) * EDIM) + k4);
                        acc[g] += w.x * h.x + w.y * h.y + w.z * h.z + w.w * h.w;
                    }
                }
            }
#pragma unroll
            for (int o = 16; o > 0; o >>= 1) {
#pragma unroll
                for (int g = 0; g < 4; ++g)
                    acc[g] += __shfl_xor_sync(0xffffffffu, acc[g], o);
            }
            if (lane == 0) {
                float I = acc[0] + bs0, F = acc[1] + bs1;
                float G = acc[2] + bs2, O = acc[3] + bs3;
                c_reg = sigf(F) * c_reg + sigf(I) * tanhf(G);
                float h2 = sigf(O) * tanhf(c_reg);
                d_dech[u] = h2;
                size_t off = dir ? (size_t)OFF_RECR : (size_t)OFF_RECF;
                out[off + (size_t)(TSEQ - 2 - s) * EDIM + m] = h2;
            }
        }
        if (s < TSEQ - 3) grid_barrier(NBLK, sense);
    }
}

// ---------------- launch ------------------------------------------------------
extern "C" void kernel_launch(void* const* d_in, const int* in_sizes, int n_in,
                              void* d_out, int out_size) {
    (void)in_sizes; (void)n_in; (void)out_size;
    const int*   x       = (const int*)d_in[0];
    const int*   Vg      = (const int*)d_in[1];
    const int*   Jg      = (const int*)d_in[2];
    const float* emb     = (const float*)d_in[3];
    const float* emb_Vg  = (const float*)d_in[4];
    const float* emb_Jg  = (const float*)d_in[5];
    const float* enc_Wih = (const float*)d_in[6];
    const float* enc_Whh = (const float*)d_in[7];
    const float* enc_bih = (const float*)d_in[8];
    const float* enc_bhh = (const float*)d_in[9];
    const float* cls_W   = (const float*)d_in[10];
    const float* cls_b   = (const float*)d_in[11];
    const float* latf_W  = (const float*)d_in[12];
    const float* latf_b  = (const float*)d_in[13];
    const float* latr_W  = (const float*)d_in[14];
    const float* latr_b  = (const float*)d_in[15];
    const float* mix_W   = (const float*)d_in[16];
    const float* mix_b   = (const float*)d_in[17];
    const float* recf_Wih = (const float*)d_in[18];
    const float* recf_Whh = (const float*)d_in[19];
    const float* recf_bih = (const float*)d_in[20];
    const float* recf_bhh = (const float*)d_in[21];
    const float* recr_Wih = (const float*)d_in[22];
    const float* recr_Whh = (const float*)d_in[23];
    const float* recr_bih = (const float*)d_in[24];
    const float* recr_bhh = (const float*)d_in[25];
    float* out = (float*)d_out;

    cudaFuncSetAttribute(k_encoder, cudaFuncAttributeMaxDynamicSharedMemorySize, ENC_SMEM);
    cudaFuncSetAttribute(k_decoder, cudaFuncAttributeMaxDynamicSharedMemorySize, DEC_SMEM);

    k_gather<<<TSEQ, 256>>>(x, emb, out);
    k_gemm_pre<<<dim3(G4H / 128, TSEQ / 64), 256>>>(enc_Wih, enc_bih, enc_bhh);
    k_wsum_small<<<(DEC_STREAM * 4 * (EDIM / 4) + 255) / 256, 256>>>(
        recr_Wih, recr_Whh, recf_bih, recf_bhh, recr_bih, recr_bhh);
    k_encoder<<<NBLK, NTHR, ENC_SMEM>>>(enc_Whh);
    k_head1<<<32, 256>>>(cls_W, cls_b, latf_W, latf_b, latr_W, latr_b);
    k_head2<<<1, 256>>>(mix_W, mix_b, emb_Vg, emb_Jg, Vg, Jg, emb, out);
    k_decoder<<<NBLK, NTHR, DEC_SMEM>>>(recf_Wih, recf_Whh, recr_Wih, recr_Whh, emb, out);
}

// round 16
// speedup vs baseline: 1.0104x; 1.0018x over previous
#include <cuda_runtime.h>
#include <math.h>

#define TSEQ 256
#define EDIM 1024
#define HDIM 2048
#define G4H  8192
#define G4E  4096
#define CLSD 512
#define MIXD 384
#define NBLK 148
#define NTHR 512

#define ENC_RES 6                      // fp32 units resident per encoder block
#define ENC_RES_TOT (NBLK*ENC_RES)     // 888
#define ENC_SPLIT 124                  // blocks with 8 streamed units (rest 7)

#define DEC_RES 13                     // fp32 units resident per decoder block
#define DEC_RES_TOT (NBLK*DEC_RES)     // 1924
#define DEC_STREAM (2*EDIM - DEC_RES_TOT) // 124

#define ENC_SMEM (ENC_RES*4*HDIM*4 + 2*HDIM*4)            // 212992
#define DEC_SMEM (DEC_RES*4*EDIM*4 + 2*EDIM*4 + 2*EDIM*4) // 229376

// output layout offsets (float elements)
#define OFF_LATF 0
#define OFF_LATR 640
#define OFF_RECF 1280
#define OFF_RECR (1280 + TSEQ*EDIM)
#define OFF_EMBF (OFF_RECR + TSEQ*EDIM)
#define OFF_EMBR (OFF_EMBF + TSEQ*EDIM)

// ---------------- scratch ----------------------------------------------------
__device__ __align__(16) float d_embf[TSEQ*EDIM];
__device__ __align__(16) float d_gpre[TSEQ*G4H];   // layout: [t][unit m][gate 0..3]
__device__ __align__(16) float d_h[2*HDIM];
__device__ __align__(16) float d_hc0[2*EDIM];
__device__ __align__(16) float d_dech[2*EDIM];
__device__ __align__(16) float d_Wsum[2u*G4E*EDIM];     // only streamed rows used
__device__ __align__(16) float d_bsumd[2*G4E];
__device__ __align__(16) float d_common[CLSD];
__device__ __align__(16) float d_latf[CLSD];
__device__ __align__(16) float d_latr[CLSD];

__device__ unsigned g_bar_count = 0;
__device__ unsigned g_bar_sense = 0;

// R5-proven barrier (exact)
__device__ __forceinline__ void grid_barrier(unsigned nblk, unsigned& sense) {
    __syncthreads();
    if (threadIdx.x == 0) {
        unsigned s = sense ^ 1u;
        sense = s;
        __threadfence();
        if (atomicAdd(&g_bar_count, 1u) == nblk - 1u) {
            atomicExch(&g_bar_count, 0u);
            __threadfence();
            atomicExch(&g_bar_sense, s);
        } else {
            while (atomicAdd(&g_bar_sense, 0u) != s) { __nanosleep(32); }
        }
    }
    __syncthreads();
}

__device__ __forceinline__ float sigf(float x) { return 1.0f / (1.0f + expf(-x)); }

// ---------------- K1: embedding gather ---------------------------------------
__global__ void k_gather(const int* __restrict__ x, const float* __restrict__ emb,
                         float* __restrict__ out) {
    int t = blockIdx.x;
    int row = x[t];
    const float4* src = (const float4*)(emb + (size_t)row * EDIM);
    float4* dE = (float4*)(d_embf + (size_t)t * EDIM);
    float4* oF = (float4*)(out + OFF_EMBF + (size_t)t * EDIM);
    float4* oR = (float4*)(out + OFF_EMBR + (size_t)(TSEQ - 1 - t) * EDIM);
    for (int i = threadIdx.x; i < EDIM / 4; i += blockDim.x) {
        float4 v = src[i];
        dE[i] = v; oF[i] = v; oR[i] = v;
    }
}

// ---------------- K2: gpre = Wih@emb_f + bih + bhh  (128x64 tile, 8x4/thr) ---
// writes TRANSPOSED layout d_gpre[t][m][gate]
__global__ void k_gemm_pre(const float* __restrict__ Wih,
                           const float* __restrict__ bih,
                           const float* __restrict__ bhh) {
    __shared__ float As[16][132];
    __shared__ float Bs[16][68];
    int tid = threadIdx.x;
    int jb = blockIdx.x * 128, tb = blockIdx.y * 64;
    int tx = tid & 15, ty = tid >> 4;

    float acc[4][8];
#pragma unroll
    for (int n = 0; n < 4; ++n)
#pragma unroll
        for (int i = 0; i < 8; ++i) acc[n][i] = 0.f;

    for (int k0 = 0; k0 < EDIM; k0 += 16) {
#pragma unroll
        for (int q = 0; q < 2; ++q) {
            int idx = tid * 2 + q;
            int row = idx >> 2, kv = idx & 3;
            float4 a = __ldg((const float4*)(Wih + (size_t)(jb + row) * EDIM + k0 + kv * 4));
            As[kv * 4 + 0][row] = a.x; As[kv * 4 + 1][row] = a.y;
            As[kv * 4 + 2][row] = a.z; As[kv * 4 + 3][row] = a.w;
        }
        {
            int tl = tid >> 2, kv = tid & 3;
            float4 b = __ldg((const float4*)(d_embf + (size_t)(tb + tl) * EDIM + k0 + kv * 4));
            Bs[kv * 4 + 0][tl] = b.x; Bs[kv * 4 + 1][tl] = b.y;
            Bs[kv * 4 + 2][tl] = b.z; Bs[kv * 4 + 3][tl] = b.w;
        }
        __syncthreads();
#pragma unroll
        for (int k = 0; k < 16; ++k) {
            float a0[8], b0[4];
            float4 av0 = *(const float4*)&As[k][tx * 8];
            float4 av1 = *(const float4*)&As[k][tx * 8 + 4];
            a0[0] = av0.x; a0[1] = av0.y; a0[2] = av0.z; a0[3] = av0.w;
            a0[4] = av1.x; a0[5] = av1.y; a0[6] = av1.z; a0[7] = av1.w;
            float4 bv = *(const float4*)&Bs[k][ty * 4];
            b0[0] = bv.x; b0[1] = bv.y; b0[2] = bv.z; b0[3] = bv.w;
#pragma unroll
            for (int n = 0; n < 4; ++n)
#pragma unroll
                for (int i = 0; i < 8; ++i)
                    acc[n][i] += a0[i] * b0[n];
        }
        __syncthreads();
    }

#pragma unroll
    for (int n = 0; n < 4; ++n) {
        int t = tb + ty * 4 + n;
#pragma unroll
        for (int i = 0; i < 8; ++i) {
            int j = jb + tx * 8 + i;
            int g = j >> 11;          // gate
            int mu = j & 2047;        // unit
            d_gpre[(size_t)t * G4H + (size_t)mu * 4 + g] =
                acc[n][i] + __ldg(&bih[j]) + __ldg(&bhh[j]);
        }
    }
}

// ---------------- K2b: wsum for STREAMED decoder units only + bias sums ------
__global__ void k_wsum_small(const float* __restrict__ wr_ih, const float* __restrict__ wr_hh,
                             const float* __restrict__ bf_ih, const float* __restrict__ bf_hh,
                             const float* __restrict__ br_ih, const float* __restrict__ br_hh) {
    int gt = blockIdx.x * blockDim.x + threadIdx.x;
    const int NV = DEC_STREAM * 4 * (EDIM / 4);
    if (gt < NV) {
        int r = gt >> 8;
        int k4 = gt & 255;
        int su = r >> 2, g = r & 3;
        int mm = (DEC_RES_TOT - EDIM) + su;
        size_t row = (size_t)(g * EDIM + mm) * EDIM;
        float4 a = __ldg((const float4*)(wr_ih + row) + k4);
        float4 b = __ldg((const float4*)(wr_hh + row) + k4);
        float4 s;
        s.x = a.x + b.x; s.y = a.y + b.y; s.z = a.z + b.z; s.w = a.w + b.w;
        *((float4*)(d_Wsum + (size_t)G4E * EDIM + row) + k4) = s;
    }
    if (gt < G4E) {
        d_bsumd[gt] = bf_ih[gt] + bf_hh[gt];
        d_bsumd[G4E + gt] = br_ih[gt] + br_hh[gt];
    }
}

// ---------------- K3: encoder persistent (R15 + streamed double-buffer) ------
__global__ void __launch_bounds__(NTHR, 1) k_encoder(const float* __restrict__ Whh) {
    extern __shared__ char esm[];
    float* sm_w = (float*)esm;
    float* sh_h = (float*)(esm + ENC_RES * 4 * HDIM * 4);

    int bid = blockIdx.x, tid = threadIdx.x;
    int warp = tid >> 5, lane = tid & 31;

    for (int i = tid; i < ENC_RES * 4 * HDIM / 4; i += NTHR) {
        int off = i * 4;
        int ul = off >> 13;
        int rem = off & 8191;
        int g = rem >> 11;
        int k = rem & 2047;
        int grow = g * HDIM + bid * ENC_RES + ul;
        ((float4*)sm_w)[i] = __ldg((const float4*)(Whh + (size_t)grow * HDIM + k));
    }

    unsigned sense = (tid == 0) ? atomicAdd(&g_bar_sense, 0u) : 0u;

    for (int i = bid * NTHR + tid; i < 2 * HDIM; i += NBLK * NTHR) d_h[i] = 0.f;

    int s_b = (bid < ENC_SPLIT) ? 8 : 7;
    int sbase = ENC_RES_TOT + bid * 7 + (bid < ENC_SPLIT ? bid : ENC_SPLIT);
    int u_b = ENC_RES + s_b;

    bool active = (warp < u_b);
    bool resident = (warp < ENC_RES);
    int m = resident ? (bid * ENC_RES + warp) : (sbase + warp - ENC_RES);
    if (!active) m = 0;

    float cf = 0.f, cr = 0.f;

    grid_barrier(NBLK, sense);

    const float4* hf4 = (const float4*)sh_h;
    const float4* hr4 = (const float4*)(sh_h + HDIM);

    for (int t = 0; t < TSEQ; ++t) {
        for (int i = tid; i < (2 * HDIM) / 4; i += NTHR)
            ((float4*)sh_h)[i] = __ldcg(((const float4*)d_h) + i);
        __syncthreads();

        if (active) {
            float gpf0 = 0, gpf1 = 0, gpf2 = 0, gpf3 = 0;
            float gpr0 = 0, gpr1 = 0, gpr2 = 0, gpr3 = 0;
            if (lane == 0) {
                float4 gf = __ldg((const float4*)(d_gpre + (size_t)t * G4H + (size_t)m * 4));
                float4 gr = __ldg((const float4*)(d_gpre + (size_t)(TSEQ - 1 - t) * G4H + (size_t)m * 4));
                gpf0 = gf.x; gpf1 = gf.y; gpf2 = gf.z; gpf3 = gf.w;
                gpr0 = gr.x; gpr1 = gr.y; gpr2 = gr.z; gpr3 = gr.w;
            }

            float accf[4] = {0.f, 0.f, 0.f, 0.f};
            float accr[4] = {0.f, 0.f, 0.f, 0.f};
            if (resident) {
                const float4* wsm = (const float4*)sm_w;
#pragma unroll
                for (int it = 0; it < 16; ++it) {
                    int k4 = it * 32 + lane;
                    float4 hf = hf4[k4];
                    float4 hr = hr4[k4];
#pragma unroll
                    for (int g = 0; g < 4; ++g) {
                        float4 w = wsm[(warp * 4 + g) * 512 + k4];
                        accf[g] += w.x * hf.x + w.y * hf.y + w.z * hf.z + w.w * hf.w;
                        accr[g] += w.x * hr.x + w.y * hr.y + w.z * hr.z + w.w * hr.w;
                    }
                }
            } else {
                const float4* w0 = (const float4*)(Whh + (size_t)(0 * HDIM + m) * HDIM);
                const float4* w1 = (const float4*)(Whh + (size_t)(1 * HDIM + m) * HDIM);
                const float4* w2 = (const float4*)(Whh + (size_t)(2 * HDIM + m) * HDIM);
                const float4* w3 = (const float4*)(Whh + (size_t)(3 * HDIM + m) * HDIM);
                // register double-buffer: prefetch next iteration's weights
                float4 nw0 = __ldg(w0 + lane);
                float4 nw1 = __ldg(w1 + lane);
                float4 nw2 = __ldg(w2 + lane);
                float4 nw3 = __ldg(w3 + lane);
#pragma unroll
                for (int it = 0; it < 16; ++it) {
                    int k4 = it * 32 + lane;
                    float4 cw0 = nw0, cw1 = nw1, cw2 = nw2, cw3 = nw3;
                    if (it < 15) {
                        int kn = k4 + 32;
                        nw0 = __ldg(w0 + kn);
                        nw1 = __ldg(w1 + kn);
                        nw2 = __ldg(w2 + kn);
                        nw3 = __ldg(w3 + kn);
                    }
                    float4 hf = hf4[k4];
                    float4 hr = hr4[k4];
                    accf[0] += cw0.x * hf.x + cw0.y * hf.y + cw0.z * hf.z + cw0.w * hf.w;
                    accr[0] += cw0.x * hr.x + cw0.y * hr.y + cw0.z * hr.z + cw0.w * hr.w;
                    accf[1] += cw1.x * hf.x + cw1.y * hf.y + cw1.z * hf.z + cw1.w * hf.w;
                    accr[1] += cw1.x * hr.x + cw1.y * hr.y + cw1.z * hr.z + cw1.w * hr.w;
                    accf[2] += cw2.x * hf.x + cw2.y * hf.y + cw2.z * hf.z + cw2.w * hf.w;
                    accr[2] += cw2.x * hr.x + cw2.y * hr.y + cw2.z * hr.z + cw2.w * hr.w;
                    accf[3] += cw3.x * hf.x + cw3.y * hf.y + cw3.z * hf.z + cw3.w * hf.w;
                    accr[3] += cw3.x * hr.x + cw3.y * hr.y + cw3.z * hr.z + cw3.w * hr.w;
                }
            }
#pragma unroll
            for (int o = 16; o > 0; o >>= 1) {
#pragma unroll
                for (int g = 0; g < 4; ++g) {
                    accf[g] += __shfl_xor_sync(0xffffffffu, accf[g], o);
                    accr[g] += __shfl_xor_sync(0xffffffffu, accr[g], o);
                }
            }
            if (lane == 0) {
                float I = accf[0] + gpf0, F = accf[1] + gpf1;
                float G = accf[2] + gpf2, O = accf[3] + gpf3;
                cf = sigf(F) * cf + sigf(I) * tanhf(G);
                d_h[m] = sigf(O) * tanhf(cf);
                I = accr[0] + gpr0; F = accr[1] + gpr1;
                G = accr[2] + gpr2; O = accr[3] + gpr3;
                cr = sigf(F) * cr + sigf(I) * tanhf(G);
                d_h[HDIM + m] = sigf(O) * tanhf(cr);
            }
        }
        if (t < TSEQ - 1) grid_barrier(NBLK, sense);
    }
}

// ---------------- K4a: common/lat heads --------------------------------------
__global__ void k_head1(const float* __restrict__ cls_W, const float* __restrict__ cls_b,
                        const float* __restrict__ latf_W, const float* __restrict__ latf_b,
                        const float* __restrict__ latr_W, const float* __restrict__ latr_b) {
    int gw = (blockIdx.x * blockDim.x + threadIdx.x) >> 5;
    int lane = threadIdx.x & 31;
    int nw = (gridDim.x * blockDim.x) >> 5;
    for (int r = gw; r < 3 * CLSD; r += nw) {
        if (r < CLSD) {
            const float4* w = (const float4*)(cls_W + (size_t)r * (2 * HDIM));
            const float4* h = (const float4*)d_h;
            float acc = 0.f;
#pragma unroll 8
            for (int it = 0; it < (2 * HDIM) / 128; ++it) {
                int k4 = it * 32 + lane;
                float4 a = __ldg(w + k4); float4 b = h[k4];
                acc += a.x * b.x + a.y * b.y + a.z * b.z + a.w * b.w;
            }
#pragma unroll
            for (int o = 16; o > 0; o >>= 1) acc += __shfl_xor_sync(0xffffffffu, acc, o);
            if (lane == 0) d_common[r] = tanhf(acc + cls_b[r]);
        } else if (r < 2 * CLSD) {
            int rr = r - CLSD;
            const float4* w = (const float4*)(latf_W + (size_t)rr * HDIM);
            const float4* h = (const float4*)d_h;
            float acc = 0.f;
#pragma unroll 8
            for (int it = 0; it < HDIM / 128; ++it) {
                int k4 = it * 32 + lane;
                float4 a = __ldg(w + k4); float4 b = h[k4];
                acc += a.x * b.x + a.y * b.y + a.z * b.z + a.w * b.w;
            }
#pragma unroll
            for (int o = 16; o > 0; o >>= 1) acc += __shfl_xor_sync(0xffffffffu, acc, o);
            if (lane == 0) d_latf[rr] = acc + latf_b[rr];
        } else {
            int rr = r - 2 * CLSD;
            const float4* w = (const float4*)(latr_W + (size_t)rr * HDIM);
            const float4* h = (const float4*)(d_h + HDIM);
            float acc = 0.f;
#pragma unroll 8
            for (int it = 0; it < HDIM / 128; ++it) {
                int k4 = it * 32 + lane;
                float4 a = __ldg(w + k4); float4 b = h[k4];
                acc += a.x * b.x + a.y * b.y + a.z * b.z + a.w * b.w;
            }
#pragma unroll
            for (int o = 16; o > 0; o >>= 1) acc += __shfl_xor_sync(0xffffffffu, acc, o);
            if (lane == 0) d_latr[rr] = acc + latr_b[rr];
        }
    }
}

// ---------------- K4b: mix + assemble h0 / lat outputs / boundaries ----------
__global__ void k_head2(const float* __restrict__ mix_W, const float* __restrict__ mix_b,
                        const float* __restrict__ emb_Vg, const float* __restrict__ emb_Jg,
                        const int* __restrict__ Vg, const int* __restrict__ Jg,
                        const float* __restrict__ emb, float* __restrict__ out) {
    __shared__ float sm_mix[MIXD];
    int tid = threadIdx.x, warp = tid >> 5, lane = tid & 31;
    for (int r = warp; r < MIXD; r += blockDim.x / 32) {
        const float4* w = (const float4*)(mix_W + (size_t)r * CLSD);
        const float4* c = (const float4*)d_common;
        float acc = 0.f;
#pragma unroll
        for (int it = 0; it < CLSD / 128; ++it) {
            int k4 = it * 32 + lane;
            float4 a = __ldg(w + k4); float4 b = c[k4];
            acc += a.x * b.x + a.y * b.y + a.z * b.z + a.w * b.w;
        }
#pragma unroll
        for (int o = 16; o > 0; o >>= 1) acc += __shfl_xor_sync(0xffffffffu, acc, o);
        if (lane == 0) sm_mix[r] = acc + mix_b[r];
    }
    __syncthreads();
    int vgi = Vg[0], jgi = Jg[0];
    for (int i = tid; i < EDIM; i += blockDim.x) {
        float vf, vr;
        if (i < 64) { float v = emb_Vg[(size_t)vgi * 64 + i]; vf = v; vr = v; }
        else if (i < 576) { vf = d_latf[i - 64]; vr = d_latr[i - 64]; }
        else if (i < 640) { float v = emb_Jg[(size_t)jgi * 64 + (i - 576)]; vf = v; vr = v; }
        else { float v = sm_mix[i - 640]; vf = v; vr = v; }
        d_hc0[i] = vf;        d_hc0[EDIM + i] = vr;
        d_dech[i] = vf;       d_dech[EDIM + i] = vr;
        if (i < 640) { out[OFF_LATF + i] = vf; out[OFF_LATR + i] = vr; }
    }
    for (int i = tid; i < EDIM; i += blockDim.x) {
        float e0 = emb[i];
        float e1 = emb[EDIM + i];
        out[OFF_RECF + i] = e1;
        out[OFF_RECF + (size_t)(TSEQ - 1) * EDIM + i] = e0;
        out[OFF_RECR + i] = e0;
        out[OFF_RECR + (size_t)(TSEQ - 1) * EDIM + i] = e1;
    }
}

// ---------------- K5: decoder persistent (R15-exact) -------------------------
__global__ void __launch_bounds__(NTHR, 1) k_decoder(
        const float* __restrict__ Wihf, const float* __restrict__ Whhf,
        const float* __restrict__ Wihr, const float* __restrict__ Whhr,
        const float* __restrict__ emb, float* __restrict__ out) {
    extern __shared__ char dsm[];
    float* sm_w = (float*)dsm;                              // [DEC_RES][4][1024]
    float* sh_h = (float*)(dsm + DEC_RES * 4 * EDIM * 4);   // [2][1024]
    float* sh_p = sh_h + 2 * EDIM;                          // [2][1024]

    int bid = blockIdx.x, tid = threadIdx.x;
    int warp = tid >> 5, lane = tid & 31;

    for (int i = tid; i < DEC_RES * 4 * EDIM / 4; i += NTHR) {
        int off = i * 4;
        int ul = off >> 12;
        int rem = off & 4095;
        int g = rem >> 10;
        int k = rem & 1023;
        int u = bid * DEC_RES + ul;
        int dir = u >> 10, mm = u & 1023;
        const float* Wi = dir ? Wihr : Wihf;
        const float* Wh = dir ? Whhr : Whhf;
        size_t row = (size_t)(g * EDIM + mm) * EDIM;
        float4 a = __ldg((const float4*)(Wi + row + k));
        float4 b = __ldg((const float4*)(Wh + row + k));
        float4 s;
        s.x = a.x + b.x; s.y = a.y + b.y; s.z = a.z + b.z; s.w = a.w + b.w;
        ((float4*)sm_w)[i] = s;
    }
    for (int i = tid; i < (2 * EDIM) / 4; i += NTHR)
        ((float4*)sh_p)[i] = __ldg(((const float4*)emb) + i);

    unsigned sense = (tid == 0) ? atomicAdd(&g_bar_sense, 0u) : 0u;

    bool need0 = (bid * DEC_RES) < EDIM;
    bool need1 = ((bid * DEC_RES + DEC_RES - 1) >= EDIM) || (bid < DEC_STREAM);

    int u_b = DEC_RES + ((bid < DEC_STREAM) ? 1 : 0);
    bool active = (warp < u_b);
    bool resident = (warp < DEC_RES);
    int u = resident ? (bid * DEC_RES + warp) : (DEC_RES_TOT + bid);
    if (!active) u = 0;
    int dir = u >> 10;
    int m = u & 1023;
    float c_reg = 0.f;
    float bs0 = 0, bs1 = 0, bs2 = 0, bs3 = 0;
    if (active && lane == 0) {
        c_reg = __ldcg(&d_hc0[u]);
        const float* bp = d_bsumd + dir * G4E + m;
        bs0 = __ldg(bp);            bs1 = __ldg(bp + EDIM);
        bs2 = __ldg(bp + 2 * EDIM); bs3 = __ldg(bp + 3 * EDIM);
    }

    const float4* h4 = (const float4*)sh_h;
    const float4* p4 = (const float4*)sh_p;

    for (int s = 0; s < TSEQ - 2; ++s) {
        if (need0)
            for (int i = tid; i < EDIM / 4; i += NTHR)
                ((float4*)sh_h)[i] = __ldcg(((const float4*)d_dech) + i);
        if (need1)
            for (int i = tid; i < EDIM / 4; i += NTHR)
                ((float4*)sh_h)[EDIM / 4 + i] = __ldcg(((const float4*)d_dech) + EDIM / 4 + i);
        __syncthreads();

        if (active) {
            float acc[4] = {0.f, 0.f, 0.f, 0.f};
            if (s == 0) {
                const float* Wi = dir ? Wihr : Wihf;
                const float* Wh = dir ? Whhr : Whhf;
#pragma unroll
                for (int it = 0; it < 8; ++it) {
                    int k4 = it * 32 + lane;
                    float4 p = p4[dir * 256 + k4];
                    float4 h = h4[dir * 256 + k4];
#pragma unroll
                    for (int g = 0; g < 4; ++g) {
                        const float4* wi = (const float4*)(Wi + (size_t)(g * EDIM + m) * EDIM);
                        const float4* wh = (const float4*)(Wh + (size_t)(g * EDIM + m) * EDIM);
                        float4 a = __ldg(wi + k4);
                        acc[g] += a.x * p.x + a.y * p.y + a.z * p.z + a.w * p.w;
                        float4 b = __ldg(wh + k4);
                        acc[g] += b.x * h.x + b.y * h.y + b.z * h.z + b.w * h.w;
                    }
                }
            } else if (resident) {
                const float4* wsm = (const float4*)sm_w;
#pragma unroll
                for (int it = 0; it < 8; ++it) {
                    int k4 = it * 32 + lane;
                    float4 h = h4[dir * 256 + k4];
#pragma unroll
                    for (int g = 0; g < 4; ++g) {
                        float4 w = wsm[(warp * 4 + g) * 256 + k4];
                        acc[g] += w.x * h.x + w.y * h.y + w.z * h.z + w.w * h.w;
                    }
                }
            } else {
                const float* Wb = d_Wsum + (size_t)dir * G4E * EDIM;
#pragma unroll
                for (int it = 0; it < 8; ++it) {
                    int k4 = it * 32 + lane;
                    float4 h = h4[dir * 256 + k4];
#pragma unroll
                    for (int g = 0; g < 4; ++g) {
                        float4 w = __ldg((const float4*)(Wb + (size_t)(g * EDIM + m) * EDIM) + k4);
                        acc[g] += w.x * h.x + w.y * h.y + w.z * h.z + w.w * h.w;
                    }
                }
            }
#pragma unroll
            for (int o = 16; o > 0; o >>= 1) {
#pragma unroll
                for (int g = 0; g < 4; ++g)
                    acc[g] += __shfl_xor_sync(0xffffffffu, acc[g], o);
            }
            if (lane == 0) {
                float I = acc[0] + bs0, F = acc[1] + bs1;
                float G = acc[2] + bs2, O = acc[3] + bs3;
                c_reg = sigf(F) * c_reg + sigf(I) * tanhf(G);
                float h2 = sigf(O) * tanhf(c_reg);
                d_dech[u] = h2;
                size_t off = dir ? (size_t)OFF_RECR : (size_t)OFF_RECF;
                out[off + (size_t)(TSEQ - 2 - s) * EDIM + m] = h2;
            }
        }
        if (s < TSEQ - 3) grid_barrier(NBLK, sense);
    }
}

// ---------------- launch ------------------------------------------------------
extern "C" void kernel_launch(void* const* d_in, const int* in_sizes, int n_in,
                              void* d_out, int out_size) {
    (void)in_sizes; (void)n_in; (void)out_size;
    const int*   x       = (const int*)d_in[0];
    const int*   Vg      = (const int*)d_in[1];
    const int*   Jg      = (const int*)d_in[2];
    const float* emb     = (const float*)d_in[3];
    const float* emb_Vg  = (const float*)d_in[4];
    const float* emb_Jg  = (const float*)d_in[5];
    const float* enc_Wih = (const float*)d_in[6];
    const float* enc_Whh = (const float*)d_in[7];
    const float* enc_bih = (const float*)d_in[8];
    const float* enc_bhh = (const float*)d_in[9];
    const float* cls_W   = (const float*)d_in[10];
    const float* cls_b   = (const float*)d_in[11];
    const float* latf_W  = (const float*)d_in[12];
    const float* latf_b  = (const float*)d_in[13];
    const float* latr_W  = (const float*)d_in[14];
    const float* latr_b  = (const float*)d_in[15];
    const float* mix_W   = (const float*)d_in[16];
    const float* mix_b   = (const float*)d_in[17];
    const float* recf_Wih = (const float*)d_in[18];
    const float* recf_Whh = (const float*)d_in[19];
    const float* recf_bih = (const float*)d_in[20];
    const float* recf_bhh = (const float*)d_in[21];
    const float* recr_Wih = (const float*)d_in[22];
    const float* recr_Whh = (const float*)d_in[23];
    const float* recr_bih = (const float*)d_in[24];
    const float* recr_bhh = (const float*)d_in[25];
    float* out = (float*)d_out;

    cudaFuncSetAttribute(k_encoder, cudaFuncAttributeMaxDynamicSharedMemorySize, ENC_SMEM);
    cudaFuncSetAttribute(k_decoder, cudaFuncAttributeMaxDynamicSharedMemorySize, DEC_SMEM);

    k_gather<<<TSEQ, 256>>>(x, emb, out);
    k_gemm_pre<<<dim3(G4H / 128, TSEQ / 64), 256>>>(enc_Wih, enc_bih, enc_bhh);
    k_wsum_small<<<(DEC_STREAM * 4 * (EDIM / 4) + 255) / 256, 256>>>(
        recr_Wih, recr_Whh, recf_bih, recf_bhh, recr_bih, recr_bhh);
    k_encoder<<<NBLK, NTHR, ENC_SMEM>>>(enc_Whh);
    k_head1<<<32, 256>>>(cls_W, cls_b, latf_W, latf_b, latr_W, latr_b);
    k_head2<<<1, 256>>>(mix_W, mix_b, emb_Vg, emb_Jg, Vg, Jg, emb, out);
    k_decoder<<<NBLK, NTHR, DEC_SMEM>>>(recf_Wih, recf_Whh, recr_Wih, recr_Whh, emb, out);
}